// round 1
// baseline (speedup 1.0000x reference)
#include <cuda_runtime.h>
#include <cuda_bf16.h>
#include <math.h>

// ---------------------------------------------------------------------------
// Decoder layer, B=1, S=2048, D=4096, H=32, HKV=8, HD=128, FF=11008
// Outputs (concatenated in d_out): hidden [S*D], draft_attn [H*S*S], true_attn [H*S*S]
// All fp32. Round 1: correct baseline with tiled FFMA SGEMM + fused epilogues.
// ---------------------------------------------------------------------------

#define S_LEN 2048
#define D_DIM 4096
#define H_HEADS 32
#define HKV_HEADS 8
#define HD_DIM 128
#define FF_DIM 11008
#define GAMMA_C 64.0f
#define EPS_C 1e-5f

// ---- scratch offsets (floats) ----
#define SD   (2048LL*4096LL)        // 8,388,608
#define SKV  (2048LL*1024LL)        // 2,097,152
#define SH   (32LL*2048LL*128LL)    // 8,388,608
#define SFF  (2048LL*11008LL)       // 22,544,384

#define O_X    0LL
#define O_Q    (O_X  + SD)
#define O_K    (O_Q  + SD)
#define O_V    (O_K  + SKV)
#define O_QR   (O_V  + SKV)
#define O_KR   (O_QR + SD)
#define O_QH   (O_KR + SKV)
#define O_KH   (O_QH + SH)
#define O_AO   (O_KH + SH)
#define O_H1   (O_AO + SD)
#define O_Y    (O_H1 + SD)
#define O_G    (O_Y  + SD)
#define O_U    (O_G  + SFF)
#define O_COS  (O_U  + SFF)
#define O_SIN  (O_COS + 2048LL*64LL)
#define SCRATCH_TOTAL (O_SIN + 2048LL*64LL)

__device__ float g_scratch[SCRATCH_TOTAL];

// ---------------------------------------------------------------------------
// RoPE tables in fp64 (matches reference's float64 table build)
// ---------------------------------------------------------------------------
__global__ void rope_table_kernel(float* cosT, float* sinT) {
    int s = blockIdx.x;
    int i = threadIdx.x; // 0..63
    double inv = exp(-(double)i * (log(10000.0) / 64.0));
    double ang = (double)s * inv;
    double sv, cv;
    sincos(ang, &sv, &cv);
    cosT[s * 64 + i] = (float)cv;
    sinT[s * 64 + i] = (float)sv;
}

// ---------------------------------------------------------------------------
// RMSNorm: out = x * rsqrt(mean(x^2) + eps) * w       (row = 4096)
// ---------------------------------------------------------------------------
__global__ void rmsnorm_kernel(const float* __restrict__ x,
                               const float* __restrict__ w,
                               float* __restrict__ out) {
    int s = blockIdx.x;
    const float* row = x + (long long)s * D_DIM;
    float* orow = out + (long long)s * D_DIM;
    int tid = threadIdx.x;
    float ss = 0.f;
    for (int i = tid; i < D_DIM; i += 256) {
        float v = row[i];
        ss += v * v;
    }
    __shared__ float red[256];
    red[tid] = ss;
    __syncthreads();
    for (int o = 128; o > 0; o >>= 1) {
        if (tid < o) red[tid] += red[tid + o];
        __syncthreads();
    }
    float inv = rsqrtf(red[0] / (float)D_DIM + EPS_C);
    for (int i = tid; i < D_DIM; i += 256)
        orow[i] = row[i] * inv * w[i];
}

// ---------------------------------------------------------------------------
// RoPE apply: per (s, head) row of HD=128
// ---------------------------------------------------------------------------
__global__ void rope_apply_kernel(const float* __restrict__ in,
                                  float* __restrict__ out,
                                  const float* __restrict__ cosT,
                                  const float* __restrict__ sinT,
                                  int nHeads) {
    int s = blockIdx.x;
    int h = blockIdx.y;
    int d = threadIdx.x; // 0..127
    int ld = nHeads * HD_DIM;
    long long base = (long long)s * ld + h * HD_DIM;
    float x = in[base + d];
    float other = (d < 64) ? -in[base + d + 64] : in[base + d - 64];
    float c = cosT[s * 64 + (d & 63)];
    float sn = sinT[s * 64 + (d & 63)];
    out[base + d] = x * c + other * sn;
}

// ---------------------------------------------------------------------------
// Generic tiled SGEMM: C = op(A @ B') with epilogue
//   TRANSB=false: C[m,n] = sum_k A[m,k]*B[k,n]
//   TRANSB=true : C[m,n] = sum_k A[m,k]*B[n,k]
// EPI: 0 store, 1 alpha*acc, 2 hash-sat (z=alpha*acc; z/(1+|z|)), 3 acc+R[idx]
// Batched via blockIdx.z with per-operand stride and repeat divisor.
// Assumes M%128==0, N%128==0, K%8==0, all pointers/lds 16B-friendly.
// ---------------------------------------------------------------------------
#define BM 128
#define BN 128
#define BK 8

template <bool TRANSB, int EPI>
__global__ __launch_bounds__(256)
void gemm_kernel(const float* __restrict__ A, const float* __restrict__ B,
                 float* __restrict__ C, const float* __restrict__ R,
                 int M, int N, int K, int lda, int ldb, int ldc,
                 long long strideA, int aRep,
                 long long strideB, int bRep,
                 long long strideC, float alpha) {
    int z = blockIdx.z;
    A += (long long)(z / aRep) * strideA;
    B += (long long)(z / bRep) * strideB;
    C += (long long)z * strideC;

    __shared__ __align__(16) float As[BK][BM];
    __shared__ __align__(16) float Bs[BK][BN];

    int tid = threadIdx.x;
    int row0 = blockIdx.y * BM;
    int col0 = blockIdx.x * BN;

    int aRow = tid >> 1;         // 0..127
    int aCol = (tid & 1) * 4;    // 0 or 4
    int bRowNN = tid >> 5;       // 0..7
    int bColNN = (tid & 31) * 4; // 0..124

    int ty = tid >> 4;           // 0..15
    int tx = tid & 15;           // 0..15

    float acc[8][8];
#pragma unroll
    for (int i = 0; i < 8; i++)
#pragma unroll
        for (int j = 0; j < 8; j++) acc[i][j] = 0.f;

    for (int k0 = 0; k0 < K; k0 += BK) {
        float4 av = *(const float4*)(A + (long long)(row0 + aRow) * lda + k0 + aCol);
        As[aCol + 0][aRow] = av.x;
        As[aCol + 1][aRow] = av.y;
        As[aCol + 2][aRow] = av.z;
        As[aCol + 3][aRow] = av.w;
        if (TRANSB) {
            float4 bv = *(const float4*)(B + (long long)(col0 + aRow) * ldb + k0 + aCol);
            Bs[aCol + 0][aRow] = bv.x;
            Bs[aCol + 1][aRow] = bv.y;
            Bs[aCol + 2][aRow] = bv.z;
            Bs[aCol + 3][aRow] = bv.w;
        } else {
            float4 bv = *(const float4*)(B + (long long)(k0 + bRowNN) * ldb + col0 + bColNN);
            *(float4*)&Bs[bRowNN][bColNN] = bv;
        }
        __syncthreads();
#pragma unroll
        for (int k = 0; k < BK; k++) {
            float4 a0 = *(const float4*)&As[k][ty * 8];
            float4 a1 = *(const float4*)&As[k][ty * 8 + 4];
            float4 b0 = *(const float4*)&Bs[k][tx * 8];
            float4 b1 = *(const float4*)&Bs[k][tx * 8 + 4];
            float ar[8] = {a0.x, a0.y, a0.z, a0.w, a1.x, a1.y, a1.z, a1.w};
            float br[8] = {b0.x, b0.y, b0.z, b0.w, b1.x, b1.y, b1.z, b1.w};
#pragma unroll
            for (int i = 0; i < 8; i++)
#pragma unroll
                for (int j = 0; j < 8; j++) acc[i][j] += ar[i] * br[j];
        }
        __syncthreads();
    }

    int rbase = row0 + ty * 8;
    int cbase = col0 + tx * 8;
#pragma unroll
    for (int i = 0; i < 8; i++) {
        long long rowoff = (long long)(rbase + i) * ldc + cbase;
#pragma unroll
        for (int jj = 0; jj < 2; jj++) {
            float4 v;
            float vv[4];
#pragma unroll
            for (int j = 0; j < 4; j++) {
                float a = acc[i][jj * 4 + j];
                if (EPI == 1) {
                    a *= alpha;
                } else if (EPI == 2) {
                    a *= alpha;
                    a = a / (1.f + fabsf(a));
                }
                vv[j] = a;
            }
            if (EPI == 3) {
                float4 r = *(const float4*)(R + rowoff + jj * 4);
                vv[0] += r.x; vv[1] += r.y; vv[2] += r.z; vv[3] += r.w;
            }
            v.x = vv[0]; v.y = vv[1]; v.z = vv[2]; v.w = vv[3];
            *(float4*)(C + rowoff + jj * 4) = v;
        }
    }
}

// ---------------------------------------------------------------------------
// Causal softmax over true_attn rows + P@V, writes attn_out [S, H*HD]
// block = (s, h), 128 threads (thread d owns output dim d)
// ---------------------------------------------------------------------------
__global__ __launch_bounds__(128)
void softmax_pv_kernel(const float* __restrict__ trueAttn,
                       const float* __restrict__ v,
                       float* __restrict__ out) {
    int s = blockIdx.x;
    int h = blockIdx.y;
    int tid = threadIdx.x;
    const float* row = trueAttn + ((long long)h * S_LEN + s) * S_LEN;
    int len = s + 1;

    __shared__ float red[128];
    __shared__ float pbuf[256];

    // pass 1: max
    float m = -1e30f;
    for (int t = tid; t < len; t += 128) m = fmaxf(m, row[t]);
    red[tid] = m;
    __syncthreads();
    for (int o = 64; o > 0; o >>= 1) {
        if (tid < o) red[tid] = fmaxf(red[tid], red[tid + o]);
        __syncthreads();
    }
    m = red[0];
    __syncthreads();

    // pass 2: staged exp + accumulate
    const float* vbase = v + (long long)(h >> 2) * HD_DIM + tid;
    float acc = 0.f, psum = 0.f;
    for (int t0 = 0; t0 < len; t0 += 256) {
        int cl = min(256, len - t0);
        for (int j = tid; j < cl; j += 128) {
            float p = __expf(row[t0 + j] - m);
            pbuf[j] = p;
            psum += p;
        }
        __syncthreads();
#pragma unroll 8
        for (int j = 0; j < cl; j++)
            acc += pbuf[j] * vbase[(long long)(t0 + j) * (HKV_HEADS * HD_DIM)];
        __syncthreads();
    }
    red[tid] = psum;
    __syncthreads();
    for (int o = 64; o > 0; o >>= 1) {
        if (tid < o) red[tid] += red[tid + o];
        __syncthreads();
    }
    float sum = red[0];
    out[(long long)s * D_DIM + h * HD_DIM + tid] = acc / sum;
}

// ---------------------------------------------------------------------------
// SwiGLU: t = silu(g) * u  (in-place into g)
// ---------------------------------------------------------------------------
__global__ void swiglu_kernel(float* __restrict__ g, const float* __restrict__ u,
                              long long n) {
    long long i = (long long)blockIdx.x * blockDim.x + threadIdx.x;
    long long stride = (long long)gridDim.x * blockDim.x;
    for (; i < n; i += stride) {
        float x = g[i];
        float sig = 1.f / (1.f + __expf(-x));
        g[i] = x * sig * u[i];
    }
}

// ---------------------------------------------------------------------------
// launch
// ---------------------------------------------------------------------------
extern "C" void kernel_launch(void* const* d_in, const int* in_sizes, int n_in,
                              void* d_out, int out_size) {
    const float* hidden_states = (const float*)d_in[0];
    const float* ln1_w = (const float*)d_in[1];
    const float* ln2_w = (const float*)d_in[2];
    const float* Wq = (const float*)d_in[3];
    const float* Wk = (const float*)d_in[4];
    const float* Wv = (const float*)d_in[5];
    const float* Wo = (const float*)d_in[6];
    const float* rot_mat = (const float*)d_in[7];
    const float* Wg = (const float*)d_in[8];
    const float* Wu = (const float*)d_in[9];
    const float* Wd = (const float*)d_in[10];

    float* out = (float*)d_out;
    float* out_hidden = out;
    float* out_draft = out + SD;
    float* out_true = out + SD + (long long)H_HEADS * S_LEN * S_LEN;

    float* sc = nullptr;
    cudaGetSymbolAddress((void**)&sc, g_scratch);
    float* g_x  = sc + O_X;
    float* g_q  = sc + O_Q;
    float* g_k  = sc + O_K;
    float* g_v  = sc + O_V;
    float* g_qr = sc + O_QR;
    float* g_kr = sc + O_KR;
    float* g_qh = sc + O_QH;
    float* g_kh = sc + O_KH;
    float* g_ao = sc + O_AO;
    float* g_h1 = sc + O_H1;
    float* g_y  = sc + O_Y;
    float* g_g  = sc + O_G;
    float* g_u  = sc + O_U;
    float* g_cos = sc + O_COS;
    float* g_sin = sc + O_SIN;

    const float scale = 0.08838834764831843f; // 1/sqrt(128)

    // RoPE tables
    rope_table_kernel<<<S_LEN, 64>>>(g_cos, g_sin);

    // ln1
    rmsnorm_kernel<<<S_LEN, 256>>>(hidden_states, ln1_w, g_x);

    // QKV projections
    gemm_kernel<false, 0><<<dim3(32, 16, 1), 256>>>(
        g_x, Wq, g_q, nullptr, S_LEN, 4096, 4096, 4096, 4096, 4096,
        0, 1, 0, 1, 0, 0.f);
    gemm_kernel<false, 0><<<dim3(8, 16, 1), 256>>>(
        g_x, Wk, g_k, nullptr, S_LEN, 1024, 4096, 4096, 1024, 1024,
        0, 1, 0, 1, 0, 0.f);
    gemm_kernel<false, 0><<<dim3(8, 16, 1), 256>>>(
        g_x, Wv, g_v, nullptr, S_LEN, 1024, 4096, 4096, 1024, 1024,
        0, 1, 0, 1, 0, 0.f);

    // RoPE
    rope_apply_kernel<<<dim3(S_LEN, H_HEADS), 128>>>(g_q, g_qr, g_cos, g_sin, H_HEADS);
    rope_apply_kernel<<<dim3(S_LEN, HKV_HEADS), 128>>>(g_k, g_kr, g_cos, g_sin, HKV_HEADS);

    // LSH hash (batched per head, epilogue z/(1+|z|) with z = GAMMA*acc)
    gemm_kernel<false, 2><<<dim3(1, 16, 32), 256>>>(
        g_qr, rot_mat, g_qh, nullptr, S_LEN, 128, 128, 4096, 128, 128,
        128, 1, 128LL * 128, 1, 2048LL * 128, GAMMA_C);
    gemm_kernel<false, 2><<<dim3(1, 16, 32), 256>>>(
        g_kr, rot_mat, g_kh, nullptr, S_LEN, 128, 128, 1024, 128, 128,
        128, 4, 128LL * 128, 1, 2048LL * 128, GAMMA_C);

    // draft_attn = q_hash @ k_hash^T   (direct to output)
    gemm_kernel<true, 0><<<dim3(16, 16, 32), 256>>>(
        g_qh, g_kh, out_draft, nullptr, S_LEN, S_LEN, 128, 128, 128, S_LEN,
        2048LL * 128, 1, 2048LL * 128, 1, (long long)S_LEN * S_LEN, 0.f);

    // true_attn = scale * q_r @ k_r^T (kv-repeat via bRep=4, direct to output)
    gemm_kernel<true, 1><<<dim3(16, 16, 32), 256>>>(
        g_qr, g_kr, out_true, nullptr, S_LEN, S_LEN, 128, 4096, 1024, S_LEN,
        128, 1, 128, 4, (long long)S_LEN * S_LEN, scale);

    // causal softmax + P@V  -> attn_out [S, H*HD]
    softmax_pv_kernel<<<dim3(S_LEN, H_HEADS), 128>>>(out_true, g_v, g_ao);

    // o_proj + residual
    gemm_kernel<false, 3><<<dim3(32, 16, 1), 256>>>(
        g_ao, Wo, g_h1, hidden_states, S_LEN, 4096, 4096, 4096, 4096, 4096,
        0, 1, 0, 1, 0, 0.f);

    // ln2
    rmsnorm_kernel<<<S_LEN, 256>>>(g_h1, ln2_w, g_y);

    // MLP
    gemm_kernel<false, 0><<<dim3(86, 16, 1), 256>>>(
        g_y, Wg, g_g, nullptr, S_LEN, FF_DIM, 4096, 4096, FF_DIM, FF_DIM,
        0, 1, 0, 1, 0, 0.f);
    gemm_kernel<false, 0><<<dim3(86, 16, 1), 256>>>(
        g_y, Wu, g_u, nullptr, S_LEN, FF_DIM, 4096, 4096, FF_DIM, FF_DIM,
        0, 1, 0, 1, 0, 0.f);
    swiglu_kernel<<<4096, 256>>>(g_g, g_u, (long long)S_LEN * FF_DIM);
    gemm_kernel<false, 3><<<dim3(32, 16, 1), 256>>>(
        g_g, Wd, out_hidden, g_h1, S_LEN, 4096, FF_DIM, FF_DIM, 4096, 4096,
        0, 1, 0, 1, 0, 0.f);

    (void)in_sizes; (void)n_in; (void)out_size;
}

// round 4
// speedup vs baseline: 1.3675x; 1.3675x over previous
#include <cuda_runtime.h>
#include <cuda_bf16.h>
#include <math.h>

// ---------------------------------------------------------------------------
// Decoder layer, B=1, S=2048, D=4096, H=32, HKV=8, HD=128, FF=11008
// Round 3: tensor-core GEMMs with 3xTF32 split precision (fp32-level accuracy),
// single-pass tf32 only for the softmax-PV GEMM.
// ---------------------------------------------------------------------------

#define S_LEN 2048
#define D_DIM 4096
#define H_HEADS 32
#define HKV_HEADS 8
#define HD_DIM 128
#define FF_DIM 11008
#define GAMMA_C 64.0f
#define EPS_C 1e-5f

// ---- scratch offsets (floats) ----
#define SD   (2048LL*4096LL)
#define SKV  (2048LL*1024LL)
#define SH   (32LL*2048LL*128LL)
#define SFF  (2048LL*11008LL)

#define O_X    0LL
#define O_Q    (O_X  + SD)
#define O_K    (O_Q  + SD)
#define O_V    (O_K  + SKV)
#define O_QR   (O_V  + SKV)
#define O_KR   (O_QR + SD)
#define O_QH   (O_KR + SKV)
#define O_KH   (O_QH + SH)
#define O_AO   (O_KH + SH)
#define O_H1   (O_AO + SD)
#define O_Y    (O_H1 + SD)
#define O_G    (O_Y  + SD)
#define O_U    (O_G  + SFF)
#define O_COS  (O_U  + SFF)
#define O_SIN  (O_COS + 2048LL*64LL)
#define O_MX   (O_SIN + 2048LL*64LL)
#define SCRATCH_TOTAL (O_MX + 32LL*2048LL)

__device__ float g_scratch[SCRATCH_TOTAL];

// ---------------------------------------------------------------------------
// helpers
// ---------------------------------------------------------------------------
__device__ __forceinline__ unsigned f2tf(float x) {
    unsigned r;
    asm("cvt.rna.tf32.f32 %0, %1;" : "=r"(r) : "f"(x));
    return r;
}

__device__ __forceinline__ void split_tf(float x, unsigned& hi, unsigned& lo) {
    hi = f2tf(x);
    lo = f2tf(x - __uint_as_float(hi));
}

__device__ __forceinline__ void mma8(float* c, const unsigned* a,
                                     unsigned b0, unsigned b1) {
    asm volatile(
        "mma.sync.aligned.m16n8k8.row.col.f32.tf32.tf32.f32 "
        "{%0,%1,%2,%3},{%4,%5,%6,%7},{%8,%9},{%0,%1,%2,%3};"
        : "+f"(c[0]), "+f"(c[1]), "+f"(c[2]), "+f"(c[3])
        : "r"(a[0]), "r"(a[1]), "r"(a[2]), "r"(a[3]), "r"(b0), "r"(b1));
}

#define CP16(d, s) asm volatile("cp.async.cg.shared.global [%0], [%1], 16;" :: "r"(d), "l"(s))
#define CP_COMMIT() asm volatile("cp.async.commit_group;")
#define CP_WAIT0()  asm volatile("cp.async.wait_group 0;")

// ---------------------------------------------------------------------------
// RoPE tables in fp64
// ---------------------------------------------------------------------------
__global__ void rope_table_kernel(float* cosT, float* sinT) {
    int s = blockIdx.x;
    int i = threadIdx.x; // 0..63
    double inv = exp(-(double)i * (log(10000.0) / 64.0));
    double ang = (double)s * inv;
    double sv, cv;
    sincos(ang, &sv, &cv);
    cosT[s * 64 + i] = (float)cv;
    sinT[s * 64 + i] = (float)sv;
}

// ---------------------------------------------------------------------------
// RMSNorm
// ---------------------------------------------------------------------------
__global__ void rmsnorm_kernel(const float* __restrict__ x,
                               const float* __restrict__ w,
                               float* __restrict__ out) {
    int s = blockIdx.x;
    const float* row = x + (long long)s * D_DIM;
    float* orow = out + (long long)s * D_DIM;
    int tid = threadIdx.x;
    float ss = 0.f;
    for (int i = tid; i < D_DIM; i += 256) {
        float v = row[i];
        ss += v * v;
    }
    __shared__ float red[256];
    red[tid] = ss;
    __syncthreads();
    for (int o = 128; o > 0; o >>= 1) {
        if (tid < o) red[tid] += red[tid + o];
        __syncthreads();
    }
    float inv = rsqrtf(red[0] / (float)D_DIM + EPS_C);
    for (int i = tid; i < D_DIM; i += 256)
        orow[i] = row[i] * inv * w[i];
}

// ---------------------------------------------------------------------------
// RoPE apply
// ---------------------------------------------------------------------------
__global__ void rope_apply_kernel(const float* __restrict__ in,
                                  float* __restrict__ out,
                                  const float* __restrict__ cosT,
                                  const float* __restrict__ sinT,
                                  int nHeads) {
    int s = blockIdx.x;
    int h = blockIdx.y;
    int d = threadIdx.x; // 0..127
    int ld = nHeads * HD_DIM;
    long long base = (long long)s * ld + h * HD_DIM;
    float x = in[base + d];
    float other = (d < 64) ? -in[base + d + 64] : in[base + d - 64];
    float c = cosT[s * 64 + (d & 63)];
    float sn = sinT[s * 64 + (d & 63)];
    out[base + d] = x * c + other * sn;
}

// ---------------------------------------------------------------------------
// row max over causal prefix of true_attn rows
// ---------------------------------------------------------------------------
__global__ void rowmax_kernel(const float* __restrict__ t, float* __restrict__ mx) {
    int r = blockIdx.x * 8 + threadIdx.y;  // 0 .. H*S-1
    int s = r & (S_LEN - 1);
    const float* row = t + (long long)r * S_LEN;
    float m = -1e30f;
    for (int i = threadIdx.x; i <= s; i += 32) m = fmaxf(m, row[i]);
#pragma unroll
    for (int o = 16; o > 0; o >>= 1) m = fmaxf(m, __shfl_xor_sync(0xffffffffu, m, o));
    if (threadIdx.x == 0) mx[r] = m;
}

// ---------------------------------------------------------------------------
// Tensor-core tf32 GEMM, 128x128x32 tile, 8 warps (2x4), warp tile 64x32.
// SPLIT=true -> 3xTF32 split precision (fp32-level accuracy).
// TRANSB=false: C[m,n] = sum_k A[m,k]*B[k,n];  true: B[n,k].
// EPI: 0 store, 1 alpha*acc, 2 hash-sat, 3 acc+R, 4 softmax-PV, 5 silu(R)*acc
// ---------------------------------------------------------------------------
#define BM 128
#define BN 128
#define BKT 32
#define ASTR 36
#define BSTR_NN 136
#define ABUF (BM * ASTR)
#define BBUF (BM * ASTR)
#define SMEM_FLOATS (2 * ABUF + 2 * BBUF + 128 + 128 + 256)
#define SMEM_BYTES (SMEM_FLOATS * 4)

template <bool TRANSB, int EPI, bool SPLIT>
__global__ __launch_bounds__(256)
void gemm_tc(const float* __restrict__ A, const float* __restrict__ B,
             float* __restrict__ C, const float* __restrict__ R,
             const float* __restrict__ stats,
             int M, int N, int K, int lda, int ldb, int ldc,
             long long strideA, int aRep,
             long long strideB, int bRep,
             long long strideC, float alpha) {
    extern __shared__ float smem[];
    float* As = smem;
    float* Bs = smem + 2 * ABUF;
    float* sMax = smem + 2 * ABUF + 2 * BBUF;
    float* sSum = sMax + 128;
    float* sPart = sSum + 128;

    int z = blockIdx.z;
    A += (long long)(z / aRep) * strideA;
    B += (long long)(z / bRep) * strideB;
    C += (long long)z * strideC;

    const int tid = threadIdx.x;
    const int row0 = blockIdx.y * BM;
    const int col0 = blockIdx.x * BN;
    const int warp = tid >> 5;
    const int lane = tid & 31;
    const int gid = lane >> 2;
    const int t4 = lane & 3;
    const int wm = (warp & 1) * 64;
    const int wn = (warp >> 1) * 32;

    if (EPI == 4) {
        if (tid < 128) {
            sMax[tid] = stats[(long long)z * M + row0 + tid];
            sSum[tid] = 0.f;
        }
        __syncthreads();
    }

    float acc[4][4][4];
#pragma unroll
    for (int i = 0; i < 4; i++)
#pragma unroll
        for (int j = 0; j < 4; j++)
#pragma unroll
            for (int q = 0; q < 4; q++) acc[i][j][q] = 0.f;

    int Kend = (EPI == 4) ? ((row0 + BM < K) ? row0 + BM : K) : K;
    int nIter = Kend / BKT;

    const int arow = tid >> 1, acol = (tid & 1) * 16;
    const int brow = tid >> 3, bcol = (tid & 7) * 16;

    // prologue: stage 0
    {
        const float* src = A + (long long)(row0 + arow) * lda + acol;
        unsigned dst = (unsigned)__cvta_generic_to_shared(As + arow * ASTR + acol);
#pragma unroll
        for (int i = 0; i < 4; i++) CP16(dst + i * 16, src + i * 4);
        if (TRANSB) {
            const float* bs = B + (long long)(col0 + arow) * ldb + acol;
            unsigned bd = (unsigned)__cvta_generic_to_shared(Bs + arow * ASTR + acol);
#pragma unroll
            for (int i = 0; i < 4; i++) CP16(bd + i * 16, bs + i * 4);
        } else {
            const float* bs = B + (long long)brow * ldb + col0 + bcol;
            unsigned bd = (unsigned)__cvta_generic_to_shared(Bs + brow * BSTR_NN + bcol);
#pragma unroll
            for (int i = 0; i < 4; i++) CP16(bd + i * 16, bs + i * 4);
        }
        CP_COMMIT();
    }

    for (int it = 0; it < nIter; it++) {
        int buf = it & 1;
        CP_WAIT0();
        __syncthreads();

        if (EPI == 4) {
            // softmax transform of A tile in smem, one exp per element
            int r = tid >> 1, c0 = (tid & 1) * 16;
            float* p = As + buf * ABUF + r * ASTR + c0;
            int gm = row0 + r;
            float mxv = sMax[r];
            int k0 = it * BKT;
            float part = 0.f;
#pragma unroll
            for (int i = 0; i < 16; i++) {
                int gk = k0 + c0 + i;
                float val = 0.f;
                if (gk <= gm) val = __expf(p[i] - mxv);
                val = __uint_as_float(f2tf(val));
                p[i] = val;
                part += val;
            }
            sPart[tid] = part;
            __syncthreads();
            if (tid < 128) sSum[tid] += sPart[2 * tid] + sPart[2 * tid + 1];
            __syncthreads();
        }

        if (it + 1 < nIter) {
            int k0n = (it + 1) * BKT;
            int nb = buf ^ 1;
            const float* src = A + (long long)(row0 + arow) * lda + k0n + acol;
            unsigned dst = (unsigned)__cvta_generic_to_shared(As + nb * ABUF + arow * ASTR + acol);
#pragma unroll
            for (int i = 0; i < 4; i++) CP16(dst + i * 16, src + i * 4);
            if (TRANSB) {
                const float* bs = B + (long long)(col0 + arow) * ldb + k0n + acol;
                unsigned bd = (unsigned)__cvta_generic_to_shared(Bs + nb * BBUF + arow * ASTR + acol);
#pragma unroll
                for (int i = 0; i < 4; i++) CP16(bd + i * 16, bs + i * 4);
            } else {
                const float* bs = B + (long long)(k0n + brow) * ldb + col0 + bcol;
                unsigned bd = (unsigned)__cvta_generic_to_shared(Bs + nb * BBUF + brow * BSTR_NN + bcol);
#pragma unroll
                for (int i = 0; i < 4; i++) CP16(bd + i * 16, bs + i * 4);
            }
            CP_COMMIT();
        }

        const float* Ab = As + buf * ABUF;
        const float* Bb = Bs + buf * BBUF;
#pragma unroll
        for (int ks = 0; ks < 4; ks++) {
            int k = ks * 8;
            unsigned afh[4][4], afl[4][4];
#pragma unroll
            for (int i = 0; i < 4; i++) {
                const float* ap = Ab + (wm + i * 16 + gid) * ASTR + k + t4;
                float x0 = ap[0], x1 = ap[8 * ASTR], x2 = ap[4], x3 = ap[8 * ASTR + 4];
                if (SPLIT) {
                    split_tf(x0, afh[i][0], afl[i][0]);
                    split_tf(x1, afh[i][1], afl[i][1]);
                    split_tf(x2, afh[i][2], afl[i][2]);
                    split_tf(x3, afh[i][3], afl[i][3]);
                } else {
                    afh[i][0] = f2tf(x0); afh[i][1] = f2tf(x1);
                    afh[i][2] = f2tf(x2); afh[i][3] = f2tf(x3);
                }
            }
            unsigned bfh[4][2], bfl[4][2];
#pragma unroll
            for (int j = 0; j < 4; j++) {
                float y0, y1;
                if (TRANSB) {
                    const float* bp = Bb + (wn + j * 8 + gid) * ASTR + k + t4;
                    y0 = bp[0]; y1 = bp[4];
                } else {
                    const float* bp = Bb + (k + t4) * BSTR_NN + wn + j * 8 + gid;
                    y0 = bp[0]; y1 = bp[4 * BSTR_NN];
                }
                if (SPLIT) {
                    split_tf(y0, bfh[j][0], bfl[j][0]);
                    split_tf(y1, bfh[j][1], bfl[j][1]);
                } else {
                    bfh[j][0] = f2tf(y0); bfh[j][1] = f2tf(y1);
                }
            }
#pragma unroll
            for (int i = 0; i < 4; i++)
#pragma unroll
                for (int j = 0; j < 4; j++) {
                    mma8(acc[i][j], afh[i], bfh[j][0], bfh[j][1]);
                    if (SPLIT) {
                        mma8(acc[i][j], afh[i], bfl[j][0], bfl[j][1]);
                        mma8(acc[i][j], afl[i], bfh[j][0], bfh[j][1]);
                    }
                }
        }
    }

    // epilogue
#pragma unroll
    for (int i = 0; i < 4; i++)
#pragma unroll
        for (int j = 0; j < 4; j++)
#pragma unroll
            for (int h = 0; h < 2; h++) {
                int lr = wm + i * 16 + gid + h * 8;
                int r = row0 + lr;
                int c = col0 + wn + j * 8 + t4 * 2;
                float v0 = acc[i][j][h * 2 + 0];
                float v1 = acc[i][j][h * 2 + 1];
                long long off = (long long)r * ldc + c;
                if (EPI == 1) {
                    v0 *= alpha; v1 *= alpha;
                } else if (EPI == 2) {
                    v0 *= alpha; v1 *= alpha;
                    v0 = v0 / (1.f + fabsf(v0));
                    v1 = v1 / (1.f + fabsf(v1));
                } else if (EPI == 3) {
                    float2 rr = *(const float2*)(R + off);
                    v0 += rr.x; v1 += rr.y;
                } else if (EPI == 4) {
                    float sdiv = sSum[lr];
                    v0 /= sdiv; v1 /= sdiv;
                } else if (EPI == 5) {
                    float2 rr = *(const float2*)(R + off);
                    float s0 = rr.x / (1.f + __expf(-rr.x));
                    float s1 = rr.y / (1.f + __expf(-rr.y));
                    v0 *= s0; v1 *= s1;
                }
                float2 o2;
                o2.x = v0; o2.y = v1;
                *(float2*)(C + off) = o2;
            }
}

// ---------------------------------------------------------------------------
// launch
// ---------------------------------------------------------------------------
extern "C" void kernel_launch(void* const* d_in, const int* in_sizes, int n_in,
                              void* d_out, int out_size) {
    const float* hidden_states = (const float*)d_in[0];
    const float* ln1_w = (const float*)d_in[1];
    const float* ln2_w = (const float*)d_in[2];
    const float* Wq = (const float*)d_in[3];
    const float* Wk = (const float*)d_in[4];
    const float* Wv = (const float*)d_in[5];
    const float* Wo = (const float*)d_in[6];
    const float* rot_mat = (const float*)d_in[7];
    const float* Wg = (const float*)d_in[8];
    const float* Wu = (const float*)d_in[9];
    const float* Wd = (const float*)d_in[10];

    float* out = (float*)d_out;
    float* out_hidden = out;
    float* out_draft = out + SD;
    float* out_true = out + SD + (long long)H_HEADS * S_LEN * S_LEN;

    float* sc = nullptr;
    cudaGetSymbolAddress((void**)&sc, g_scratch);
    float* g_x  = sc + O_X;
    float* g_q  = sc + O_Q;
    float* g_k  = sc + O_K;
    float* g_v  = sc + O_V;
    float* g_qr = sc + O_QR;
    float* g_kr = sc + O_KR;
    float* g_qh = sc + O_QH;
    float* g_kh = sc + O_KH;
    float* g_ao = sc + O_AO;
    float* g_h1 = sc + O_H1;
    float* g_y  = sc + O_Y;
    float* g_g  = sc + O_G;
    float* g_u  = sc + O_U;
    float* g_cos = sc + O_COS;
    float* g_sin = sc + O_SIN;
    float* g_mx = sc + O_MX;

    const float scale = 0.08838834764831843f; // 1/sqrt(128)

    cudaFuncSetAttribute(gemm_tc<false, 0, true>, cudaFuncAttributeMaxDynamicSharedMemorySize, SMEM_BYTES);
    cudaFuncSetAttribute(gemm_tc<false, 2, true>, cudaFuncAttributeMaxDynamicSharedMemorySize, SMEM_BYTES);
    cudaFuncSetAttribute(gemm_tc<false, 3, true>, cudaFuncAttributeMaxDynamicSharedMemorySize, SMEM_BYTES);
    cudaFuncSetAttribute(gemm_tc<false, 4, false>, cudaFuncAttributeMaxDynamicSharedMemorySize, SMEM_BYTES);
    cudaFuncSetAttribute(gemm_tc<false, 5, true>, cudaFuncAttributeMaxDynamicSharedMemorySize, SMEM_BYTES);
    cudaFuncSetAttribute(gemm_tc<true, 0, true>, cudaFuncAttributeMaxDynamicSharedMemorySize, SMEM_BYTES);
    cudaFuncSetAttribute(gemm_tc<true, 1, true>, cudaFuncAttributeMaxDynamicSharedMemorySize, SMEM_BYTES);

    rope_table_kernel<<<S_LEN, 64>>>(g_cos, g_sin);
    rmsnorm_kernel<<<S_LEN, 256>>>(hidden_states, ln1_w, g_x);

    // QKV projections (split)
    gemm_tc<false, 0, true><<<dim3(32, 16, 1), 256, SMEM_BYTES>>>(
        g_x, Wq, g_q, nullptr, nullptr, S_LEN, 4096, 4096, 4096, 4096, 4096,
        0, 1, 0, 1, 0, 0.f);
    gemm_tc<false, 0, true><<<dim3(8, 16, 1), 256, SMEM_BYTES>>>(
        g_x, Wk, g_k, nullptr, nullptr, S_LEN, 1024, 4096, 4096, 1024, 1024,
        0, 1, 0, 1, 0, 0.f);
    gemm_tc<false, 0, true><<<dim3(8, 16, 1), 256, SMEM_BYTES>>>(
        g_x, Wv, g_v, nullptr, nullptr, S_LEN, 1024, 4096, 4096, 1024, 1024,
        0, 1, 0, 1, 0, 0.f);

    // RoPE
    rope_apply_kernel<<<dim3(S_LEN, H_HEADS), 128>>>(g_q, g_qr, g_cos, g_sin, H_HEADS);
    rope_apply_kernel<<<dim3(S_LEN, HKV_HEADS), 128>>>(g_k, g_kr, g_cos, g_sin, HKV_HEADS);

    // LSH hash (split)
    gemm_tc<false, 2, true><<<dim3(1, 16, 32), 256, SMEM_BYTES>>>(
        g_qr, rot_mat, g_qh, nullptr, nullptr, S_LEN, 128, 128, 4096, 128, 128,
        128, 1, 128LL * 128, 1, 2048LL * 128, GAMMA_C);
    gemm_tc<false, 2, true><<<dim3(1, 16, 32), 256, SMEM_BYTES>>>(
        g_kr, rot_mat, g_kh, nullptr, nullptr, S_LEN, 128, 128, 1024, 128, 128,
        128, 4, 128LL * 128, 1, 2048LL * 128, GAMMA_C);

    // draft_attn = q_hash @ k_hash^T (split)
    gemm_tc<true, 0, true><<<dim3(16, 16, 32), 256, SMEM_BYTES>>>(
        g_qh, g_kh, out_draft, nullptr, nullptr, S_LEN, S_LEN, 128, 128, 128, S_LEN,
        2048LL * 128, 1, 2048LL * 128, 1, (long long)S_LEN * S_LEN, 0.f);

    // true_attn = scale * q_r @ k_r^T (split)
    gemm_tc<true, 1, true><<<dim3(16, 16, 32), 256, SMEM_BYTES>>>(
        g_qr, g_kr, out_true, nullptr, nullptr, S_LEN, S_LEN, 128, 4096, 1024, S_LEN,
        128, 1, 128, 4, (long long)S_LEN * S_LEN, scale);

    // causal row max
    rowmax_kernel<<<H_HEADS * S_LEN / 8, dim3(32, 8)>>>(out_true, g_mx);

    // PV: softmax in A-transform (single tf32)
    gemm_tc<false, 4, false><<<dim3(1, 16, 32), 256, SMEM_BYTES>>>(
        out_true, g_v, g_ao, nullptr, g_mx, S_LEN, 128, S_LEN, S_LEN, 1024, 4096,
        (long long)S_LEN * S_LEN, 1, 128, 4, 128, 0.f);

    // o_proj + residual (split)
    gemm_tc<false, 3, true><<<dim3(32, 16, 1), 256, SMEM_BYTES>>>(
        g_ao, Wo, g_h1, hidden_states, nullptr, S_LEN, 4096, 4096, 4096, 4096, 4096,
        0, 1, 0, 1, 0, 0.f);

    rmsnorm_kernel<<<S_LEN, 256>>>(g_h1, ln2_w, g_y);

    // MLP: gate, up (fused silu(g)*u), down + residual (all split)
    gemm_tc<false, 0, true><<<dim3(86, 16, 1), 256, SMEM_BYTES>>>(
        g_y, Wg, g_g, nullptr, nullptr, S_LEN, FF_DIM, 4096, 4096, FF_DIM, FF_DIM,
        0, 1, 0, 1, 0, 0.f);
    gemm_tc<false, 5, true><<<dim3(86, 16, 1), 256, SMEM_BYTES>>>(
        g_y, Wu, g_u, g_g, nullptr, S_LEN, FF_DIM, 4096, 4096, FF_DIM, FF_DIM,
        0, 1, 0, 1, 0, 0.f);
    gemm_tc<false, 3, true><<<dim3(32, 16, 1), 256, SMEM_BYTES>>>(
        g_u, Wd, out_hidden, g_h1, nullptr, S_LEN, 4096, FF_DIM, FF_DIM, 4096, 4096,
        0, 1, 0, 1, 0, 0.f);

    (void)in_sizes; (void)n_in; (void)out_size;
}